// round 2
// baseline (speedup 1.0000x reference)
#include <cuda_runtime.h>
#include <math.h>

#define TPB 128           // threads per block == cells per block
#define CH 30             // channels per cell
#define MAX_BLOCKS 8192

__device__ float g_partials[MAX_BLOCKS];
__device__ int   g_count;           // zero-initialized; reset by last block each launch

// Per-cell YOLO loss, exactly matching the jax reference math.
__device__ __forceinline__ float cell_loss(const float* __restrict__ p,
                                           const float* __restrict__ t,
                                           float gy, float gx)
{
    const float ratio = 1.0f / 7.0f;
    const float tconf = t[4];
    const float p1c = p[4], p2c = p[9];

    if (!(tconf > 0.0f)) {
        // no-object cell: only lambda_noobj * (conf1^2 + conf2^2)
        return 0.5f * (p1c * p1c + p2c * p2c);
    }

    // target abs box
    float tcx = (t[0] + gx) * ratio;
    float tcy = (t[1] + gy) * ratio;
    float tw = t[2], th = t[3];
    float tx1 = tcx - tw * 0.5f, ty1 = tcy - th * 0.5f;
    float tx2 = tcx + tw * 0.5f, ty2 = tcy + th * 0.5f;
    float areaT = (tx2 - tx1) * (ty2 - ty1);

    auto iou_with = [&](const float* b) -> float {
        float bcx = (b[0] + gx) * ratio;
        float bcy = (b[1] + gy) * ratio;
        float bw = b[2], bh = b[3];
        float x1 = bcx - bw * 0.5f, y1 = bcy - bh * 0.5f;
        float x2 = bcx + bw * 0.5f, y2 = bcy + bh * 0.5f;
        float iw = fmaxf(fminf(x2, tx2) - fmaxf(x1, tx1), 0.0f);
        float ih = fmaxf(fminf(y2, ty2) - fmaxf(y1, ty1), 0.0f);
        float inter = iw * ih;
        float area = (x2 - x1) * (y2 - y1);
        return inter / (area + areaT - inter);
    };

    float iou1 = iou_with(p);
    float iou2 = iou_with(p + 5);
    bool resp = iou1 > iou2;
    const float* pc = resp ? p : (p + 5);
    float iouS = resp ? iou1 : iou2;

    // coord xy
    float dx = pc[0] - t[0];
    float dy = pc[1] - t[1];
    // coord wh (sqrt of clipped values)
    float sw = sqrtf(fmaxf(pc[2], 1e-6f)) - sqrtf(fmaxf(t[2], 1e-6f));
    float sh = sqrtf(fmaxf(pc[3], 1e-6f)) - sqrtf(fmaxf(t[3], 1e-6f));
    float coord = 5.0f * (dx * dx + dy * dy + sw * sw + sh * sh);

    // conf (responsible predictor vs its IoU)
    float dc = pc[4] - iouS;
    float conf = dc * dc;

    // class loss over 20 channels
    float cls = 0.0f;
#pragma unroll
    for (int k = 10; k < 30; k++) {
        float d = p[k] - t[k];
        cls += d * d;
    }
    return coord + conf + cls;
}

__global__ void __launch_bounds__(TPB)
yolo_loss_fused(const float* __restrict__ predicts,
                const float* __restrict__ targets,
                int n_cells, float* __restrict__ out)
{
    __shared__ float sp[TPB * CH];   // 15360 B
    __shared__ float st[TPB * CH];   // 15360 B
    __shared__ bool  is_last;

    const int tid = threadIdx.x;
    const int tile_cell0 = blockIdx.x * TPB;
    const int cells_here = min(TPB, n_cells - tile_cell0);
    const long long float_base = (long long)tile_cell0 * CH;
    const int n_floats = cells_here * CH;

    // Cooperative coalesced load of the tile into shared memory.
    if (cells_here == TPB) {
        const float4* p4 = reinterpret_cast<const float4*>(predicts + float_base);
        const float4* t4 = reinterpret_cast<const float4*>(targets + float_base);
        float4* sp4 = reinterpret_cast<float4*>(sp);
        float4* st4 = reinterpret_cast<float4*>(st);
#pragma unroll
        for (int i = 0; i < (TPB * CH) / 4 / TPB; i++) {   // 7 full rounds
            int idx = i * TPB + tid;
            sp4[idx] = p4[idx];
            st4[idx] = t4[idx];
        }
        if (tid < 64) {                                    // 960 - 7*128 = 64
            int idx = 7 * TPB + tid;
            sp4[idx] = p4[idx];
            st4[idx] = t4[idx];
        }
    } else {
        for (int i = tid; i < n_floats; i += TPB) {
            sp[i] = predicts[float_base + i];
            st[i] = targets[float_base + i];
        }
    }
    __syncthreads();

    float loss = 0.0f;
    if (tid < cells_here) {
        int cell = tile_cell0 + tid;
        int within = cell % 49;        // (y, x) within the 7x7 grid
        int y = within / 7;
        int x = within - y * 7;
        loss = cell_loss(sp + tid * CH, st + tid * CH, (float)y, (float)x);
    }
    __syncthreads();

    // Deterministic block tree reduction (reuse sp as scratch).
    sp[tid] = loss;
    __syncthreads();
#pragma unroll
    for (int s = TPB / 2; s >= 32; s >>= 1) {
        if (tid < s) sp[tid] += sp[tid + s];
        __syncthreads();
    }
    if (tid < 32) {
        float v = sp[tid];
#pragma unroll
        for (int off = 16; off > 0; off >>= 1)
            v += __shfl_down_sync(0xFFFFFFFFu, v, off);
        if (tid == 0) {
            g_partials[blockIdx.x] = v;
            __threadfence();                       // partial visible before count bump
            int old = atomicAdd(&g_count, 1);
            is_last = (old == gridDim.x - 1);
        }
    }
    __syncthreads();

    // Last block to finish reduces all partials in a FIXED order (deterministic).
    if (is_last) {
        const int nb = gridDim.x;
        float v = 0.0f;
        // fixed-order strided accumulation; partials are L2-hot
        for (int i = tid; i < nb; i += TPB)
            v += g_partials[i];
        sp[tid] = v;
        __syncthreads();
#pragma unroll
        for (int s = TPB / 2; s >= 32; s >>= 1) {
            if (tid < s) sp[tid] += sp[tid + s];
            __syncthreads();
        }
        if (tid < 32) {
            float w = sp[tid];
#pragma unroll
            for (int off = 16; off > 0; off >>= 1)
                w += __shfl_down_sync(0xFFFFFFFFu, w, off);
            if (tid == 0) {
                out[0] = w;
                g_count = 0;                       // reset for next graph replay
            }
        }
    }
}

extern "C" void kernel_launch(void* const* d_in, const int* in_sizes, int n_in,
                              void* d_out, int out_size)
{
    const float* predicts = (const float*)d_in[0];
    const float* targets  = (const float*)d_in[1];
    float* out = (float*)d_out;

    int n_cells = in_sizes[0] / CH;            // 8192*7*7 = 401408
    int blocks = (n_cells + TPB - 1) / TPB;    // 3136
    if (blocks > MAX_BLOCKS) blocks = MAX_BLOCKS;  // safety (not hit for this shape)

    yolo_loss_fused<<<blocks, TPB>>>(predicts, targets, n_cells, out);
}

// round 4
// speedup vs baseline: 1.0391x; 1.0391x over previous
#include <cuda_runtime.h>
#include <cstdint>
#include <math.h>

#define TPB 128
#define CH 30
#define TILE_FLOATS (TPB * CH)        // 3840 floats per array per tile
#define MAXG 1184

__device__ float g_partials[MAXG];
__device__ int   g_count;             // zero-init; reset by last block each launch

__device__ __forceinline__ void cp16(unsigned int s, const void* g) {
    asm volatile("cp.async.cg.shared.global [%0], [%1], 16;" :: "r"(s), "l"(g));
}
__device__ __forceinline__ void cp_commit() {
    asm volatile("cp.async.commit_group;");
}

// Per-cell YOLO loss, matching the jax reference math.
__device__ __forceinline__ float cell_loss(const float* __restrict__ p,
                                           const float* __restrict__ t,
                                           float gy, float gx)
{
    const float ratio = 1.0f / 7.0f;
    const float tconf = t[4];
    const float p1c = p[4], p2c = p[9];

    if (!(tconf > 0.0f)) {
        return 0.5f * (p1c * p1c + p2c * p2c);   // lambda_noobj * (c1^2 + c2^2)
    }

    float tcx = (t[0] + gx) * ratio;
    float tcy = (t[1] + gy) * ratio;
    float tw = t[2], th = t[3];
    float tx1 = tcx - tw * 0.5f, ty1 = tcy - th * 0.5f;
    float tx2 = tcx + tw * 0.5f, ty2 = tcy + th * 0.5f;
    float areaT = (tx2 - tx1) * (ty2 - ty1);

    auto iou_with = [&](const float* b) -> float {
        float bcx = (b[0] + gx) * ratio;
        float bcy = (b[1] + gy) * ratio;
        float bw = b[2], bh = b[3];
        float x1 = bcx - bw * 0.5f, y1 = bcy - bh * 0.5f;
        float x2 = bcx + bw * 0.5f, y2 = bcy + bh * 0.5f;
        float iw = fmaxf(fminf(x2, tx2) - fmaxf(x1, tx1), 0.0f);
        float ih = fmaxf(fminf(y2, ty2) - fmaxf(y1, ty1), 0.0f);
        float inter = iw * ih;
        float area = (x2 - x1) * (y2 - y1);
        return inter / (area + areaT - inter);
    };

    float iou1 = iou_with(p);
    float iou2 = iou_with(p + 5);
    bool resp = iou1 > iou2;
    const float* pc = resp ? p : (p + 5);
    float iouS = resp ? iou1 : iou2;

    float dx = pc[0] - t[0];
    float dy = pc[1] - t[1];
    float sw = sqrtf(fmaxf(pc[2], 1e-6f)) - sqrtf(fmaxf(t[2], 1e-6f));
    float sh = sqrtf(fmaxf(pc[3], 1e-6f)) - sqrtf(fmaxf(t[3], 1e-6f));
    float coord = 5.0f * (dx * dx + dy * dy + sw * sw + sh * sh);

    float dc = pc[4] - iouS;
    float conf = dc * dc;

    float cls = 0.0f;
#pragma unroll
    for (int k = 10; k < 30; k++) {
        float d = p[k] - t[k];
        cls += d * d;
    }
    return coord + conf + cls;
}

__global__ void __launch_bounds__(TPB)
yolo_persistent(const float* __restrict__ predicts,
                const float* __restrict__ targets,
                int n_cells, int ntiles, float* __restrict__ out)
{
    extern __shared__ float smem[];
    // layout: [sp0 | st0 | sp1 | st1], each TILE_FLOATS
    float* spb[2] = { smem,                   smem + 2 * TILE_FLOATS };
    float* stb[2] = { smem + TILE_FLOATS,     smem + 3 * TILE_FLOATS };
    __shared__ bool is_last;

    const int tid  = threadIdx.x;
    const int bid  = blockIdx.x;
    const int grid = gridDim.x;

    // tiles handled by this block: bid, bid+grid, ... (static -> deterministic)
    const int my_n = (ntiles > bid) ? ((ntiles - bid - 1) / grid + 1) : 0;

    auto prefetch = [&](int m, int buf) {
        const int tile = bid + m * grid;
        const int c0 = tile * TPB;
        const int cells = min(TPB, n_cells - c0);
        const long long fb = (long long)c0 * CH;
        if (cells == TPB) {
            const float4* p4 = reinterpret_cast<const float4*>(predicts + fb);
            const float4* t4 = reinterpret_cast<const float4*>(targets + fb);
            unsigned int sp_s = (unsigned int)__cvta_generic_to_shared(spb[buf]);
            unsigned int st_s = (unsigned int)__cvta_generic_to_shared(stb[buf]);
#pragma unroll
            for (int i = 0; i < 7; i++) {
                int idx = i * TPB + tid;
                cp16(sp_s + idx * 16, p4 + idx);
                cp16(st_s + idx * 16, t4 + idx);
            }
            if (tid < 64) {
                int idx = 896 + tid;
                cp16(sp_s + idx * 16, p4 + idx);
                cp16(st_s + idx * 16, t4 + idx);
            }
        } else {
            // rare ragged tail: zero-fill then direct loads (uniform branch per block)
            for (int i = tid; i < TILE_FLOATS; i += TPB) {
                spb[buf][i] = 0.0f;
                stb[buf][i] = 0.0f;
            }
            __syncthreads();
            const int nf = cells * CH;
            for (int i = tid; i < nf; i += TPB) {
                spb[buf][i] = predicts[fb + i];
                stb[buf][i] = targets[fb + i];
            }
        }
    };

    float acc = 0.0f;

    if (my_n > 0) prefetch(0, 0);
    cp_commit();

    for (int m = 0; m < my_n; m++) {
        const int buf = m & 1;
        const bool has_next = (m + 1) < my_n;
        if (has_next) prefetch(m + 1, (m + 1) & 1);
        cp_commit();                               // one group per iteration (empty ok)

        if (has_next) asm volatile("cp.async.wait_group 1;");
        else          asm volatile("cp.async.wait_group 0;");
        __syncthreads();                           // tile m fully staged for all threads

        const int cell = (bid + m * grid) * TPB + tid;
        if (cell < n_cells) {
            int within = cell % 49;
            int y = within / 7;
            int x = within - y * 7;
            acc += cell_loss(spb[buf] + tid * CH, stb[buf] + tid * CH,
                             (float)y, (float)x);
        }
        __syncthreads();                           // buffer free before tile m+2 prefetch
    }

    // One block reduction at the very end (reuse smem).
    smem[tid] = acc;
    __syncthreads();
#pragma unroll
    for (int s = TPB / 2; s >= 32; s >>= 1) {
        if (tid < s) smem[tid] += smem[tid + s];
        __syncthreads();
    }
    if (tid < 32) {
        float v = smem[tid];
#pragma unroll
        for (int off = 16; off > 0; off >>= 1)
            v += __shfl_down_sync(0xFFFFFFFFu, v, off);
        if (tid == 0) {
            g_partials[bid] = v;
            __threadfence();
            int old = atomicAdd(&g_count, 1);
            is_last = (old == grid - 1);
        }
    }
    __syncthreads();

    if (is_last) {
        float v = 0.0f;
        for (int i = tid; i < grid; i += TPB)      // fixed order -> deterministic
            v += g_partials[i];
        smem[tid] = v;
        __syncthreads();
#pragma unroll
        for (int s = TPB / 2; s >= 32; s >>= 1) {
            if (tid < s) smem[tid] += smem[tid + s];
            __syncthreads();
        }
        if (tid < 32) {
            float w = smem[tid];
#pragma unroll
            for (int off = 16; off > 0; off >>= 1)
                w += __shfl_down_sync(0xFFFFFFFFu, w, off);
            if (tid == 0) {
                out[0] = w;
                g_count = 0;                       // reset for next graph replay
            }
        }
    }
}

extern "C" void kernel_launch(void* const* d_in, const int* in_sizes, int n_in,
                              void* d_out, int out_size)
{
    const float* predicts = (const float*)d_in[0];
    const float* targets  = (const float*)d_in[1];
    float* out = (float*)d_out;

    int n_cells = in_sizes[0] / CH;                  // 401408
    int ntiles  = (n_cells + TPB - 1) / TPB;         // 3136

    int blocks = 444;                                // 3 per SM x 148 SMs
    if (blocks > ntiles) blocks = ntiles;
    if (blocks > MAXG)   blocks = MAXG;

    const int smem_bytes = 4 * TILE_FLOATS * sizeof(float);  // 61440
    cudaFuncSetAttribute(yolo_persistent,
                         cudaFuncAttributeMaxDynamicSharedMemorySize, smem_bytes);

    yolo_persistent<<<blocks, TPB, smem_bytes>>>(predicts, targets,
                                                 n_cells, ntiles, out);
}